// round 4
// baseline (speedup 1.0000x reference)
#include <cuda_runtime.h>
#include <stdint.h>

#define NUM_BUCKETS 4000000
#define NUM_FIELDS  63
#define NUM_SEG     64
#define SEQ         500
#define BATCH       16384

// 0 = indices/fields are int32, 1 = int64. Set by probe kernel each launch.
__device__ int g_is64;

// Detect int32 vs int64 element width of the `indexes` buffer.
// For int64 data (positive, < 2^32), every odd 32-bit word is zero.
// For int32 data uniform in [0, 1e8), an odd word is zero with p ~= 1e-8.
// We only read the first 8192 words = 32 KB, safely inside either buffer.
__global__ void probe_dtype_kernel(const unsigned int* __restrict__ w) {
    __shared__ unsigned int s_any;
    if (threadIdx.x == 0) s_any = 0u;
    __syncthreads();
    unsigned int acc = 0u;
    for (int i = 2 * threadIdx.x + 1; i < 8192; i += 2 * blockDim.x)
        acc |= w[i];
    if (acc) atomicOr(&s_any, 1u);
    __syncthreads();
    if (threadIdx.x == 0) g_is64 = (s_any == 0u) ? 1 : 0;
}

__global__ __launch_bounds__(256) void wide_pool_kernel(
    const void* __restrict__ idx_raw,
    const void* __restrict__ fld_raw,
    const float* __restrict__ values,
    const float* __restrict__ table,
    float* __restrict__ out)
{
    __shared__ float acc[NUM_SEG];
    const int b = blockIdx.x;
    const int t = threadIdx.x;

    if (t < NUM_SEG) acc[t] = 0.0f;
    __syncthreads();

    const long base = (long)b * SEQ;
    const int is64 = g_is64;

    if (is64) {
        const unsigned long long* __restrict__ ip =
            (const unsigned long long*)idx_raw;
        const unsigned long long* __restrict__ fp =
            (const unsigned long long*)fld_raw;
        for (int l = t; l < SEQ; l += 256) {
            const long p = base + l;
            const unsigned int idx = (unsigned int)ip[p];
            const unsigned int f   = (unsigned int)fp[p];
            const float x = __ldg(&table[idx % NUM_BUCKETS]) * values[p];
            atomicAdd(&acc[f & (NUM_SEG - 1)], x);
        }
    } else {
        const unsigned int* __restrict__ ip = (const unsigned int*)idx_raw;
        const unsigned int* __restrict__ fp = (const unsigned int*)fld_raw;
        for (int l = t; l < SEQ; l += 256) {
            const long p = base + l;
            const unsigned int idx = ip[p];
            const unsigned int f   = fp[p];
            const float x = __ldg(&table[idx % NUM_BUCKETS]) * values[p];
            atomicAdd(&acc[f & (NUM_SEG - 1)], x);
        }
    }

    __syncthreads();
    // Drop segment 0 (padding field); write fields 1..63 -> out[b, f-1].
    if (t >= 1 && t < NUM_SEG)
        out[(long)b * NUM_FIELDS + (t - 1)] = acc[t];
}

extern "C" void kernel_launch(void* const* d_in, const int* in_sizes, int n_in,
                              void* d_out, int out_size) {
    // metadata order: indexes, fields, values, emb_table
    const void*  d_idx   = d_in[0];
    const void*  d_fld   = d_in[1];
    const float* d_val   = (const float*)d_in[2];
    const float* d_table = (const float*)d_in[3];
    float*       out     = (float*)d_out;

    probe_dtype_kernel<<<1, 256>>>((const unsigned int*)d_idx);
    wide_pool_kernel<<<BATCH, 256>>>(d_idx, d_fld, d_val, d_table, out);
}

// round 9
// speedup vs baseline: 1.0981x; 1.0981x over previous
#include <cuda_runtime.h>
#include <stdint.h>

#define NUM_BUCKETS 4000000u
#define NUM_FIELDS  63
#define NUM_SEG     64
#define SEQ         500
#define BATCH       16384

// 0 = indices/fields are int32, 1 = int64. Set by probe kernel each launch.
__device__ int g_is64;

// Detect int32 vs int64 element width of the `indexes` buffer.
// For int64 data (positive, < 2^32), every odd 32-bit word is zero.
// For int32 data uniform in [0, 1e8), an odd word is zero with p ~= 1e-8.
// Reads first 8192 words = 32 KB, safely inside either buffer size.
__global__ void probe_dtype_kernel(const unsigned int* __restrict__ w) {
    __shared__ unsigned int s_any;
    if (threadIdx.x == 0) s_any = 0u;
    __syncthreads();
    unsigned int acc = 0u;
    for (int i = 2 * threadIdx.x + 1; i < 8192; i += 2 * blockDim.x)
        acc |= w[i];
    if (acc) atomicOr(&s_any, 1u);
    __syncthreads();
    if (threadIdx.x == 0) g_is64 = (s_any == 0u) ? 1 : 0;
}

// One CTA per batch row. 125 active threads x 4 elements = 500.
// All stream loads are 128-bit vectors; 4 table gathers issued back-to-back
// (L2-only via __ldcg) before any consumption for MLP=4 per thread.
__global__ __launch_bounds__(128) void wide_pool_kernel(
    const void* __restrict__ idx_raw,
    const void* __restrict__ fld_raw,
    const float* __restrict__ values,
    const float* __restrict__ table,
    float* __restrict__ out)
{
    __shared__ float acc[NUM_SEG];
    const int b = blockIdx.x;
    const int t = threadIdx.x;

    if (t < NUM_SEG) acc[t] = 0.0f;
    __syncthreads();

    if (t < SEQ / 4) {
        const long base = (long)b * SEQ + (long)t * 4;  // 16B-aligned (500 % 4 == 0)

        unsigned int i0, i1, i2, i3;
        unsigned int f0, f1, f2, f3;

        if (g_is64) {
            const ulonglong2* __restrict__ ip = (const ulonglong2*)idx_raw;
            const ulonglong2* __restrict__ fp = (const ulonglong2*)fld_raw;
            const long h = base >> 1;          // base is even
            ulonglong2 ia = ip[h];
            ulonglong2 ib = ip[h + 1];
            ulonglong2 fa = fp[h];
            ulonglong2 fb = fp[h + 1];
            i0 = (unsigned int)ia.x; i1 = (unsigned int)ia.y;
            i2 = (unsigned int)ib.x; i3 = (unsigned int)ib.y;
            f0 = (unsigned int)fa.x; f1 = (unsigned int)fa.y;
            f2 = (unsigned int)fb.x; f3 = (unsigned int)fb.y;
        } else {
            const uint4* __restrict__ ip = (const uint4*)idx_raw;
            const uint4* __restrict__ fp = (const uint4*)fld_raw;
            const long q = base >> 2;          // base divisible by 4
            uint4 ia = ip[q];
            uint4 fa = fp[q];
            i0 = ia.x; i1 = ia.y; i2 = ia.z; i3 = ia.w;
            f0 = fa.x; f1 = fa.y; f2 = fa.z; f3 = fa.w;
        }

        const float4 v = *(const float4*)(values + base);

        // Issue all 4 gathers before consuming any (MLP=4). L2-only: the
        // random 16MB table has ~1% L1 hit rate; don't burn L1 fills.
        const float e0 = __ldcg(table + (i0 % NUM_BUCKETS));
        const float e1 = __ldcg(table + (i1 % NUM_BUCKETS));
        const float e2 = __ldcg(table + (i2 % NUM_BUCKETS));
        const float e3 = __ldcg(table + (i3 % NUM_BUCKETS));

        atomicAdd(&acc[f0 & (NUM_SEG - 1)], e0 * v.x);
        atomicAdd(&acc[f1 & (NUM_SEG - 1)], e1 * v.y);
        atomicAdd(&acc[f2 & (NUM_SEG - 1)], e2 * v.z);
        atomicAdd(&acc[f3 & (NUM_SEG - 1)], e3 * v.w);
    }

    __syncthreads();
    // Drop segment 0 (padding field); write fields 1..63 -> out[b, f-1].
    if (t >= 1 && t < NUM_SEG)
        out[(long)b * NUM_FIELDS + (t - 1)] = acc[t];
}

extern "C" void kernel_launch(void* const* d_in, const int* in_sizes, int n_in,
                              void* d_out, int out_size) {
    // metadata order: indexes, fields, values, emb_table
    const void*  d_idx   = d_in[0];
    const void*  d_fld   = d_in[1];
    const float* d_val   = (const float*)d_in[2];
    const float* d_table = (const float*)d_in[3];
    float*       out     = (float*)d_out;

    probe_dtype_kernel<<<1, 256>>>((const unsigned int*)d_idx);
    wide_pool_kernel<<<BATCH, 128>>>(d_idx, d_fld, d_val, d_table, out);
}